// round 5
// baseline (speedup 1.0000x reference)
#include <cuda_runtime.h>
#include <cstdint>

#define BATCH     64
#define HH        1024
#define WW        1024
#define OUTN      256
#define ROWS_PER_BLOCK 16
#define BLOCKS_PER_BATCH (HH / ROWS_PER_BLOCK)   // 64
#define QUADS_PER_ROW (WW / 4)                   // 256
#define GDEPTH 4                                  // rows per pipeline group
#define NGROUPS (ROWS_PER_BLOCK / GDEPTH)         // 4

// Per-block partials, written unconditionally every launch (no init needed).
// [BATCH][BLOCKS_PER_BATCH][7]: count, sumr, sumc, minr, maxr, minc, maxc
__device__ int g_part[BATCH][BLOCKS_PER_BATCH][7];
// Per-batch arrival tickets; finishing block resets to 0 -> replay-deterministic.
__device__ unsigned int g_ticket[BATCH];

__global__ __launch_bounds__(256) void gss_fused_kernel(const float4* __restrict__ mask,
                                                        const float* __restrict__ Wm,
                                                        const float* __restrict__ bias,
                                                        float* __restrict__ out) {
    const int blk   = blockIdx.x;
    const int batch = blk / BLOCKS_PER_BATCH;
    const int bslot = blk % BLOCKS_PER_BATCH;
    const int row0  = bslot * ROWS_PER_BLOCK;
    const int t     = threadIdx.x;            // one float4 column-quad per thread
    const int col0  = t * 4;

    const float4* base = mask
        + (size_t)batch * (HH * QUADS_PER_ROW)
        + (size_t)row0 * QUADS_PER_ROW
        + t;

    // fp accumulators (exact: all integer-valued, small)
    float cnt_f = 0.0f;   // total hits
    float sr_f  = 0.0f;   // sum of row * row_count
    float wc_f  = 0.0f;   // sum of (i1 + 2*i2 + 3*i3)
    unsigned c0 = 0, c1 = 0, c2 = 0, c3 = 0;  // per-column "ever nonzero"
    unsigned rm = 0;                           // per-row hit bitmap (16 rows)

    // Software pipeline: keep 4-8 LDG.128 in flight per thread continuously.
    float4 buf[2][GDEPTH];
    #pragma unroll
    for (int r = 0; r < GDEPTH; ++r)
        buf[0][r] = __ldcs(base + (size_t)r * QUADS_PER_ROW);

    #pragma unroll
    for (int g = 0; g < NGROUPS; ++g) {
        const int cur = g & 1, nxt = cur ^ 1;
        if (g + 1 < NGROUPS) {
            #pragma unroll
            for (int r = 0; r < GDEPTH; ++r)
                buf[nxt][r] = __ldcs(base + (size_t)((g + 1) * GDEPTH + r) * QUADS_PER_ROW);
        }
        #pragma unroll
        for (int r = 0; r < GDEPTH; ++r) {
            const int rr = g * GDEPTH + r;
            float4 v = buf[cur][r];
            float t1 = v.x + v.y;
            float t2 = v.z + v.w;
            float rc = t1 + t2;                   // row hit count (0..4)
            cnt_f += rc;
            sr_f = fmaf((float)(row0 + rr), rc, sr_f);
            wc_f += v.y;
            wc_f = fmaf(v.z, 2.0f, wc_f);
            wc_f = fmaf(v.w, 3.0f, wc_f);
            c0 |= __float_as_uint(v.x);
            c1 |= __float_as_uint(v.y);
            c2 |= __float_as_uint(v.z);
            c3 |= __float_as_uint(v.w);
            if (rc != 0.0f) rm |= (1u << rr);
        }
    }

    // ---- per-thread epilogue: recover bbox + exact int stats ----
    int count = (int)cnt_f;
    int sumr  = (int)sr_f;
    int sumc  = col0 * count + (int)wc_f;
    unsigned cb = (c0 ? 1u : 0u) | (c1 ? 2u : 0u) | (c2 ? 4u : 0u) | (c3 ? 8u : 0u);
    int minc = cb ? (col0 + (__ffs(cb) - 1)) : WW;
    int maxc = cb ? (col0 + (31 - __clz(cb))) : -1;
    int minr = rm ? (row0 + (__ffs(rm) - 1)) : HH;
    int maxr = rm ? (row0 + (31 - __clz(rm))) : -1;

    // ---- intra-block reduction ----
    const unsigned full = 0xFFFFFFFFu;
    #pragma unroll
    for (int off = 16; off > 0; off >>= 1) {
        count += __shfl_down_sync(full, count, off);
        sumr  += __shfl_down_sync(full, sumr,  off);
        sumc  += __shfl_down_sync(full, sumc,  off);
        minr  = min(minr, __shfl_down_sync(full, minr, off));
        maxr  = max(maxr, __shfl_down_sync(full, maxr, off));
        minc  = min(minc, __shfl_down_sync(full, minc, off));
        maxc  = max(maxc, __shfl_down_sync(full, maxc, off));
    }

    __shared__ int s_cnt[8], s_sr[8], s_sc[8], s_mnr[8], s_mxr[8], s_mnc[8], s_mxc[8];
    __shared__ int s_is_last;
    __shared__ float s_feat[6];
    int wid = t >> 5, lid = t & 31;
    if (lid == 0) {
        s_cnt[wid] = count; s_sr[wid] = sumr; s_sc[wid] = sumc;
        s_mnr[wid] = minr;  s_mxr[wid] = maxr;
        s_mnc[wid] = minc;  s_mxc[wid] = maxc;
    }
    __syncthreads();

    if (t < 8) {
        count = s_cnt[t]; sumr = s_sr[t]; sumc = s_sc[t];
        minr = s_mnr[t]; maxr = s_mxr[t];
        minc = s_mnc[t]; maxc = s_mxc[t];
        #pragma unroll
        for (int off = 4; off > 0; off >>= 1) {
            count += __shfl_down_sync(0xFF, count, off);
            sumr  += __shfl_down_sync(0xFF, sumr,  off);
            sumc  += __shfl_down_sync(0xFF, sumc,  off);
            minr  = min(minr, __shfl_down_sync(0xFF, minr, off));
            maxr  = max(maxr, __shfl_down_sync(0xFF, maxr, off));
            minc  = min(minc, __shfl_down_sync(0xFF, minc, off));
            maxc  = max(maxc, __shfl_down_sync(0xFF, maxc, off));
        }
        if (t == 0) {
            int* p = g_part[batch][bslot];
            p[0] = count; p[1] = sumr; p[2] = sumc;
            p[3] = minr;  p[4] = maxr;
            p[5] = minc;  p[6] = maxc;
            __threadfence();
            unsigned old = atomicAdd(&g_ticket[batch], 1u);
            s_is_last = (old == BLOCKS_PER_BATCH - 1);
        }
    }
    __syncthreads();

    if (!s_is_last) return;

    // ---- last block of this batch: reduce 64 partials + emit outputs ----
    {
        __threadfence();  // acquire: make all blocks' partials visible
        if (t < BLOCKS_PER_BATCH) {
            const int* p = g_part[batch][t];
            count = p[0]; sumr = p[1]; sumc = p[2];
            minr = p[3]; maxr = p[4]; minc = p[5]; maxc = p[6];
        } else {
            count = 0; sumr = 0; sumc = 0;
            minr = HH; maxr = -1; minc = WW; maxc = -1;
        }
        #pragma unroll
        for (int off = 16; off > 0; off >>= 1) {
            count += __shfl_down_sync(full, count, off);
            sumr  += __shfl_down_sync(full, sumr,  off);
            sumc  += __shfl_down_sync(full, sumc,  off);
            minr  = min(minr, __shfl_down_sync(full, minr, off));
            maxr  = max(maxr, __shfl_down_sync(full, maxr, off));
            minc  = min(minc, __shfl_down_sync(full, minc, off));
            maxc  = max(maxc, __shfl_down_sync(full, maxc, off));
        }
        if (lid == 0 && wid < 2) {
            s_cnt[wid] = count; s_sr[wid] = sumr; s_sc[wid] = sumc;
            s_mnr[wid] = minr;  s_mxr[wid] = maxr;
            s_mnc[wid] = minc;  s_mxc[wid] = maxc;
        }
    }
    __syncthreads();

    if (t == 0) {
        count = s_cnt[0] + s_cnt[1];
        sumr  = s_sr[0]  + s_sr[1];
        sumc  = s_sc[0]  + s_sc[1];
        minr  = min(s_mnr[0], s_mnr[1]);
        maxr  = max(s_mxr[0], s_mxr[1]);
        minc  = min(s_mnc[0], s_mnc[1]);
        maxc  = max(s_mxc[0], s_mxc[1]);

        float f0 = 0.f, f1 = 0.f, f2 = 0.f, f3 = 0.f, f4 = 0.f, f5 = 0.f;
        if (count > 0) {
            float fa = (float)count;
            float cr = (float)sumr / fa;
            float cc = (float)sumc / fa;
            float height = (float)(maxr - minr);
            float width  = (float)(maxc - minc);
            const float hw = (float)HH * (float)WW;
            f0 = cr / (float)HH;
            f1 = cc / (float)WW;
            f2 = height / (float)HH;
            f3 = width / (float)WW;
            f4 = fa / hw;
            f5 = height * width / hw;
        }
        s_feat[0] = f0; s_feat[1] = f1; s_feat[2] = f2;
        s_feat[3] = f3; s_feat[4] = f4; s_feat[5] = f5;
        g_ticket[batch] = 0;  // reset for next graph replay
    }
    __syncthreads();

    // 256 threads -> 256 output elements for this batch
    const float* wrow = Wm + t * 6;
    float acc = bias[t];
    acc = fmaf(s_feat[0], wrow[0], acc);
    acc = fmaf(s_feat[1], wrow[1], acc);
    acc = fmaf(s_feat[2], wrow[2], acc);
    acc = fmaf(s_feat[3], wrow[3], acc);
    acc = fmaf(s_feat[4], wrow[4], acc);
    acc = fmaf(s_feat[5], wrow[5], acc);
    out[batch * OUTN + t] = acc;
}

extern "C" void kernel_launch(void* const* d_in, const int* in_sizes, int n_in,
                              void* d_out, int out_size) {
    const float* mask = (const float*)d_in[0];   // (64,1,1024,1024) fp32
    const float* Wm   = (const float*)d_in[1];   // (256,6) fp32
    const float* bias = (const float*)d_in[2];   // (256,) fp32
    float* out = (float*)d_out;                  // (64,256) fp32

    gss_fused_kernel<<<BATCH * BLOCKS_PER_BATCH, 256>>>((const float4*)mask, Wm, bias, out);
}

// round 6
// speedup vs baseline: 1.0333x; 1.0333x over previous
#include <cuda_runtime.h>
#include <cstdint>

#define BATCH     64
#define HH        1024
#define WW        1024
#define OUTN      256
#define ROWS_PER_BLOCK 32
#define BLOCKS_PER_BATCH (HH / ROWS_PER_BLOCK)   // 32
#define ROW_BYTES (WW * 4)                        // 4096
#define STAGES     4
#define CHUNK_ROWS 4
#define CHUNK_BYTES (CHUNK_ROWS * ROW_BYTES)      // 16384
#define NCHUNKS    (ROWS_PER_BLOCK / CHUNK_ROWS)  // 8
#define SMEM_BUF_BYTES (STAGES * CHUNK_BYTES)     // 65536
#define SMEM_TOTAL (SMEM_BUF_BYTES + STAGES * 8)  // + mbarriers

// Per-block partials, written unconditionally every launch (no init needed).
__device__ int g_part[BATCH][BLOCKS_PER_BATCH][7];
// Per-batch arrival tickets; finishing block resets to 0 -> replay-deterministic.
__device__ unsigned int g_ticket[BATCH];

__device__ __forceinline__ uint32_t smem_u32(const void* p) {
    return (uint32_t)__cvta_generic_to_shared(p);
}
__device__ __forceinline__ void mbar_init(uint32_t mbar, uint32_t cnt) {
    asm volatile("mbarrier.init.shared.b64 [%0], %1;" :: "r"(mbar), "r"(cnt) : "memory");
}
__device__ __forceinline__ void mbar_expect_tx(uint32_t mbar, uint32_t bytes) {
    asm volatile("mbarrier.arrive.expect_tx.shared.b64 _, [%0], %1;"
                 :: "r"(mbar), "r"(bytes) : "memory");
}
__device__ __forceinline__ void mbar_wait(uint32_t mbar, uint32_t parity) {
    asm volatile(
        "{\n\t.reg .pred P1;\n\t"
        "WAIT_LOOP_%=:\n\t"
        "mbarrier.try_wait.parity.acquire.cta.shared::cta.b64 P1, [%0], %1, 0x989680;\n\t"
        "@P1 bra.uni WAIT_DONE_%=;\n\t"
        "bra.uni WAIT_LOOP_%=;\n\t"
        "WAIT_DONE_%=:\n\t}"
        :: "r"(mbar), "r"(parity) : "memory");
}
__device__ __forceinline__ void bulk_g2s(uint32_t smem_addr, const void* gmem,
                                         uint32_t bytes, uint32_t mbar) {
    asm volatile(
        "cp.async.bulk.shared::cta.global.mbarrier::complete_tx::bytes [%0], [%1], %2, [%3];"
        :: "r"(smem_addr), "l"(gmem), "r"(bytes), "r"(mbar) : "memory");
}

__global__ __launch_bounds__(256) void gss_tma_kernel(const float* __restrict__ mask,
                                                      const float* __restrict__ Wm,
                                                      const float* __restrict__ bias,
                                                      float* __restrict__ out) {
    extern __shared__ char smem[];
    char* bufs = smem;                                   // STAGES x CHUNK_BYTES
    uint32_t mbar0 = smem_u32(smem + SMEM_BUF_BYTES);    // STAGES mbarriers

    const int blk   = blockIdx.x;
    const int batch = blk / BLOCKS_PER_BATCH;
    const int bslot = blk % BLOCKS_PER_BATCH;
    const int row0  = bslot * ROWS_PER_BLOCK;
    const int t     = threadIdx.x;
    const int col0  = t * 4;

    // This block's 128 KB region is fully contiguous in GMEM.
    const char* gsrc = (const char*)mask
        + ((size_t)batch * HH + row0) * ROW_BYTES;

    if (t == 0) {
        #pragma unroll
        for (int s = 0; s < STAGES; ++s) mbar_init(mbar0 + s * 8, 1);
    }
    __syncthreads();

    // Prime the pipeline: fill all stages.
    if (t == 0) {
        #pragma unroll
        for (int c = 0; c < STAGES; ++c) {
            mbar_expect_tx(mbar0 + c * 8, CHUNK_BYTES);
            bulk_g2s(smem_u32(bufs + c * CHUNK_BYTES), gsrc + (size_t)c * CHUNK_BYTES,
                     CHUNK_BYTES, mbar0 + c * 8);
        }
    }

    // fp accumulators (exact: all integer-valued, small)
    float cnt_f = 0.0f, sr_f = 0.0f, wc_f = 0.0f;
    unsigned c0 = 0, c1 = 0, c2 = 0, c3 = 0;  // per-column "ever nonzero"
    unsigned rm = 0;                           // per-row hit bitmap (32 rows)

    #pragma unroll
    for (int c = 0; c < NCHUNKS; ++c) {
        const int s  = c % STAGES;
        const int ph = (c / STAGES) & 1;
        mbar_wait(mbar0 + s * 8, ph);

        const char* cb = bufs + s * CHUNK_BYTES;
        #pragma unroll
        for (int r = 0; r < CHUNK_ROWS; ++r) {
            const int rr = c * CHUNK_ROWS + r;
            float4 v = ((const float4*)(cb + r * ROW_BYTES))[t];
            float t1 = v.x + v.y;
            float t2 = v.z + v.w;
            float rc = t1 + t2;                   // row hit count (0..4)
            cnt_f += rc;
            sr_f = fmaf((float)(row0 + rr), rc, sr_f);
            wc_f += v.y;
            wc_f = fmaf(v.z, 2.0f, wc_f);
            wc_f = fmaf(v.w, 3.0f, wc_f);
            c0 |= __float_as_uint(v.x);
            c1 |= __float_as_uint(v.y);
            c2 |= __float_as_uint(v.z);
            c3 |= __float_as_uint(v.w);
            if (rc != 0.0f) rm |= (1u << rr);
        }
        __syncthreads();  // all consumers done with buffer s
        if (t == 0 && c + STAGES < NCHUNKS) {
            mbar_expect_tx(mbar0 + s * 8, CHUNK_BYTES);
            bulk_g2s(smem_u32(bufs + s * CHUNK_BYTES),
                     gsrc + (size_t)(c + STAGES) * CHUNK_BYTES,
                     CHUNK_BYTES, mbar0 + s * 8);
        }
    }

    // ---- per-thread epilogue: recover bbox + exact int stats ----
    int count = (int)cnt_f;
    int sumr  = (int)sr_f;
    int sumc  = col0 * count + (int)wc_f;
    unsigned cbm = (c0 ? 1u : 0u) | (c1 ? 2u : 0u) | (c2 ? 4u : 0u) | (c3 ? 8u : 0u);
    int minc = cbm ? (col0 + (__ffs(cbm) - 1)) : WW;
    int maxc = cbm ? (col0 + (31 - __clz(cbm))) : -1;
    int minr = rm ? (row0 + (__ffs(rm) - 1)) : HH;
    int maxr = rm ? (row0 + (31 - __clz(rm))) : -1;

    // ---- intra-block reduction ----
    const unsigned full = 0xFFFFFFFFu;
    #pragma unroll
    for (int off = 16; off > 0; off >>= 1) {
        count += __shfl_down_sync(full, count, off);
        sumr  += __shfl_down_sync(full, sumr,  off);
        sumc  += __shfl_down_sync(full, sumc,  off);
        minr  = min(minr, __shfl_down_sync(full, minr, off));
        maxr  = max(maxr, __shfl_down_sync(full, maxr, off));
        minc  = min(minc, __shfl_down_sync(full, minc, off));
        maxc  = max(maxc, __shfl_down_sync(full, maxc, off));
    }

    __shared__ int s_cnt[8], s_sr[8], s_sc[8], s_mnr[8], s_mxr[8], s_mnc[8], s_mxc[8];
    __shared__ int s_is_last;
    __shared__ float s_feat[6];
    int wid = t >> 5, lid = t & 31;
    if (lid == 0) {
        s_cnt[wid] = count; s_sr[wid] = sumr; s_sc[wid] = sumc;
        s_mnr[wid] = minr;  s_mxr[wid] = maxr;
        s_mnc[wid] = minc;  s_mxc[wid] = maxc;
    }
    __syncthreads();

    if (t < 8) {
        count = s_cnt[t]; sumr = s_sr[t]; sumc = s_sc[t];
        minr = s_mnr[t]; maxr = s_mxr[t];
        minc = s_mnc[t]; maxc = s_mxc[t];
        #pragma unroll
        for (int off = 4; off > 0; off >>= 1) {
            count += __shfl_down_sync(0xFF, count, off);
            sumr  += __shfl_down_sync(0xFF, sumr,  off);
            sumc  += __shfl_down_sync(0xFF, sumc,  off);
            minr  = min(minr, __shfl_down_sync(0xFF, minr, off));
            maxr  = max(maxr, __shfl_down_sync(0xFF, maxr, off));
            minc  = min(minc, __shfl_down_sync(0xFF, minc, off));
            maxc  = max(maxc, __shfl_down_sync(0xFF, maxc, off));
        }
        if (t == 0) {
            int* p = g_part[batch][bslot];
            p[0] = count; p[1] = sumr; p[2] = sumc;
            p[3] = minr;  p[4] = maxr;
            p[5] = minc;  p[6] = maxc;
            __threadfence();
            unsigned old = atomicAdd(&g_ticket[batch], 1u);
            s_is_last = (old == BLOCKS_PER_BATCH - 1);
        }
    }
    __syncthreads();

    if (!s_is_last) return;

    // ---- last block of this batch: reduce 32 partials + emit outputs ----
    if (t < 32) {
        __threadfence();  // acquire: make all blocks' partials visible
        const int* p = g_part[batch][t];
        count = p[0]; sumr = p[1]; sumc = p[2];
        minr = p[3]; maxr = p[4]; minc = p[5]; maxc = p[6];
        #pragma unroll
        for (int off = 16; off > 0; off >>= 1) {
            count += __shfl_down_sync(full, count, off);
            sumr  += __shfl_down_sync(full, sumr,  off);
            sumc  += __shfl_down_sync(full, sumc,  off);
            minr  = min(minr, __shfl_down_sync(full, minr, off));
            maxr  = max(maxr, __shfl_down_sync(full, maxr, off));
            minc  = min(minc, __shfl_down_sync(full, minc, off));
            maxc  = max(maxc, __shfl_down_sync(full, maxc, off));
        }
        if (t == 0) {
            float f0 = 0.f, f1 = 0.f, f2 = 0.f, f3 = 0.f, f4 = 0.f, f5 = 0.f;
            if (count > 0) {
                float fa = (float)count;
                float cr = (float)sumr / fa;
                float cc = (float)sumc / fa;
                float height = (float)(maxr - minr);
                float width  = (float)(maxc - minc);
                const float hw = (float)HH * (float)WW;
                f0 = cr / (float)HH;
                f1 = cc / (float)WW;
                f2 = height / (float)HH;
                f3 = width / (float)WW;
                f4 = fa / hw;
                f5 = height * width / hw;
            }
            s_feat[0] = f0; s_feat[1] = f1; s_feat[2] = f2;
            s_feat[3] = f3; s_feat[4] = f4; s_feat[5] = f5;
            g_ticket[batch] = 0;  // reset for next graph replay
        }
    }
    __syncthreads();

    const float* wrow = Wm + t * 6;
    float acc = bias[t];
    acc = fmaf(s_feat[0], wrow[0], acc);
    acc = fmaf(s_feat[1], wrow[1], acc);
    acc = fmaf(s_feat[2], wrow[2], acc);
    acc = fmaf(s_feat[3], wrow[3], acc);
    acc = fmaf(s_feat[4], wrow[4], acc);
    acc = fmaf(s_feat[5], wrow[5], acc);
    out[batch * OUTN + t] = acc;
}

extern "C" void kernel_launch(void* const* d_in, const int* in_sizes, int n_in,
                              void* d_out, int out_size) {
    const float* mask = (const float*)d_in[0];   // (64,1,1024,1024) fp32
    const float* Wm   = (const float*)d_in[1];   // (256,6) fp32
    const float* bias = (const float*)d_in[2];   // (256,) fp32
    float* out = (float*)d_out;                  // (64,256) fp32

    cudaFuncSetAttribute(gss_tma_kernel,
                         cudaFuncAttributeMaxDynamicSharedMemorySize, SMEM_TOTAL);
    gss_tma_kernel<<<BATCH * BLOCKS_PER_BATCH, 256, SMEM_TOTAL>>>(mask, Wm, bias, out);
}